// round 13
// baseline (speedup 1.0000x reference)
#include <cuda_runtime.h>
#include <cuda_fp16.h>
#include <cstdint>

// Problem constants
#define BB    8
#define NTOK  16384
#define KCOMP 64
#define CGRP  256       // N / K
#define CDIM  8192      // C_OUT == C_IN
#define IPTS  512       // points per group = K * 8
#define NGRP  (BB * CGRP)       // 2048
#define HK    32        // k's per CTA (K split in 2)
#define NWRITERS 128    // groups whose even CTA initializes y = bias

// Row: 32 halfs (dens, scaled e*1024) + float2 point
#define PITCH_W 18      // words per row (16 dens words + 2 point words)

// Points shared from even sibling to odd sibling
__device__ float2 g_pts[NGRP * IPTS];   // 8 MB
// g_sync[grp]  = points-ready flag for group grp
// g_sync[NGRP] = bias-done counter
__device__ int g_sync[NGRP + 1];

// Bare MUFU.EX2 (no libm wrapper)
__device__ __forceinline__ float ex2_approx(float t)
{
    float r;
    asm("ex2.approx.ftz.f32 %0, %1;" : "=f"(r) : "f"(t));
    return r;
}

// ---------------------------------------------------------------------------
// threefry2x32 (20 rounds)
// ---------------------------------------------------------------------------
__host__ __device__ __forceinline__
void threefry2x32(uint32_t k0, uint32_t k1, uint32_t x0, uint32_t x1,
                  uint32_t& y0, uint32_t& y1)
{
    uint32_t ks2 = k0 ^ k1 ^ 0x1BD11BDAu;
#define TF_RND(r) { x0 += x1; x1 = (x1 << (r)) | (x1 >> (32 - (r))); x1 ^= x0; }
    x0 += k0; x1 += k1;
    TF_RND(13) TF_RND(15) TF_RND(26) TF_RND(6)
    x0 += k1;  x1 += ks2 + 1u;
    TF_RND(17) TF_RND(29) TF_RND(16) TF_RND(24)
    x0 += ks2; x1 += k0 + 2u;
    TF_RND(13) TF_RND(15) TF_RND(26) TF_RND(6)
    x0 += k0;  x1 += k1 + 3u;
    TF_RND(17) TF_RND(29) TF_RND(16) TF_RND(24)
    x0 += k1;  x1 += ks2 + 4u;
    TF_RND(13) TF_RND(15) TF_RND(26) TF_RND(6)
    x0 += ks2; x1 += k0 + 5u;
#undef TF_RND
    y0 = x0; y1 = x1;
}

// jax partitionable random_bits: counter (0, f); bits = w0 ^ w1
__device__ __forceinline__
float jax_uniform_at(uint32_t k0, uint32_t k1, uint32_t f)
{
    uint32_t y0, y1;
    threefry2x32(k0, k1, 0u, f, y0, y1);
    uint32_t bits = y0 ^ y1;
    return __uint_as_float((bits >> 9) | 0x3F800000u) - 1.0f;
}

// ---------------------------------------------------------------------------
// Single fused kernel. CTA pair (2g, 2g+1) covers group g's two k-halves.
// Even CTA generates points; odd CTA consumes them via g_pts + flag.
// ---------------------------------------------------------------------------
__global__ void __launch_bounds__(512, 4)
sparse_fused_kernel(const float* __restrict__ x,
                    const float* __restrict__ means,
                    const float* __restrict__ sigmas,
                    const float* __restrict__ values,
                    const float* __restrict__ bias,
                    float* __restrict__ y,
                    uint32_t kg0, uint32_t kg1, uint32_t kl0, uint32_t kl1)
{
    __shared__ __align__(16) float vno[HK];
    __shared__ float mm0g[KCOMP], mm1g[KCOMP];   // means (even: all; odd: half)
    __shared__ float qq0[HK], qq1[HK];
    __shared__ float us[IPTS];                   // uniforms * (1-eps) (even only)
    __shared__ uint32_t rows[IPTS * PITCH_W];    // 36864 B

    const int bx   = blockIdx.x;
    const int grp  = bx >> 1;
    const int even = !(bx & 1);
    const int koff = (bx & 1) * HK;
    const int b    = grp >> 8;
    const int tid  = threadIdx.x;

    const float OME   = (float)(1.0 - 1e-6);
    const float NHL2E = -0.72134752044448170f;   // -0.5*log2(e)
    const float TEN   = 10.0f;                   // folds the *1024 fp16 scale

    // ---- bias init (even CTAs of first 128 groups; all wave-1) ----
    if (even && grp < NWRITERS) {
        int o = (grp << 9) | tid;
        y[o] = bias[o & (CDIM - 1)];
    }

    // ---- params ----
    if (even) {
        if (tid < KCOMP) {   // all 64 means needed for point generation
            size_t mb = ((size_t)grp * KCOMP + tid) * 2;
            mm0g[tid] = means[mb + 0];
            mm1g[tid] = means[mb + 1];
        }
    } else {
        if (tid < HK) {
            size_t mb = ((size_t)grp * KCOMP + koff + tid) * 2;
            mm0g[koff + tid] = means[mb + 0];
            mm1g[koff + tid] = means[mb + 1];
        }
    }
    if (tid < HK) {
        size_t sb = ((size_t)grp * KCOMP + koff + tid) * 2;
        qq0[tid] = NHL2E / (1e-6f + sigmas[sb + 0]);
        qq1[tid] = NHL2E / (1e-6f + sigmas[sb + 1]);
    }

    if (even) {
        // ---- uniforms: one threefry per thread ----
        {
            uint32_t s  = (uint32_t)tid >> 8;
            uint32_t f  = (uint32_t)grp * 256u + ((uint32_t)tid & 255u);
            uint32_t a0 = s ? kl0 : kg0;
            uint32_t a1 = s ? kl1 : kg1;
            us[tid] = jax_uniform_at(a0, a1, f) * OME;
        }
        __syncthreads();

        // ---- generate this group's 512 points ----
        const int k = tid >> 3;
        const int j = tid & 7;
        float m0 = mm0g[k];
        float m1 = mm1g[k];
        float r0, r1;
        if (j < 4) {
            r0 = (j < 2)        ? floorf(m0) : ceilf(m0);
            r1 = ((j & 1) == 0) ? floorf(m1) : ceilf(m1);
        } else {
            int base = (((j >> 1) & 1) << 8) + 4 * k + ((j & 1) << 1);
            float u0 = us[base];
            float u1 = us[base + 1];
            if (j < 6) {
                r0 = floorf(u0 * 8192.0f);
                r1 = floorf(u1 * 8192.0f);
            } else {
                float mr0 = rintf(m0), mr1 = rintf(m1);
                float lo0 = mr0 - 8.0f;
                if (lo0 < 0.0f) lo0 = 0.0f;
                if (mr0 + 8.0f > 8192.0f) lo0 = 8176.0f;
                float lo1 = mr1 - 8.0f;
                if (lo1 < 0.0f) lo1 = 0.0f;
                if (mr1 + 8.0f > 8192.0f) lo1 = 8176.0f;
                r0 = floorf(u0 * 16.0f + lo0);
                r1 = floorf(u1 * 16.0f + lo1);
            }
        }
        r0 = fminf(fmaxf(r0, 0.0f), 8191.0f);
        r1 = fminf(fmaxf(r1, 0.0f), 8191.0f);
        float2 pt = make_float2(r0, r1);
        *(float2*)(rows + tid * PITCH_W + 16) = pt;   // local copy
        g_pts[grp * IPTS + tid] = pt;                 // publish to sibling

        // ---- release: points (and bias) visible, then set flags ----
        __threadfence();
        __syncthreads();
        if (tid == 0) {
            atomicExch(&g_sync[grp], 1);
            if (grp < NWRITERS) atomicAdd(&g_sync[NGRP], 1);
        }
        __syncthreads();
    } else {
        // ---- acquire sibling's points ----
        if (tid == 0) {
            while (*(volatile int*)&g_sync[grp] == 0) { }
            __threadfence();
        }
        __syncthreads();
        float2 pt = __ldcg(&g_pts[grp * IPTS + tid]);
        *(float2*)(rows + tid * PITCH_W + 16) = pt;
        __syncthreads();
    }

    // ---- density: warp = 2 components (ka, kb); lane = io over 32 points ----
    {
        const int p  = tid >> 5;         // 0..15 (k-pair)
        const int io = tid & 31;
        const int ka = 2 * p, kb = ka + 1;
        const float ma0 = mm0g[koff + ka], ma1 = mm1g[koff + ka];
        const float mb0 = mm0g[koff + kb], mb1 = mm1g[koff + kb];
        const float qa0 = qq0[ka], qa1 = qq1[ka];
        const float qb0 = qq0[kb], qb1 = qq1[kb];
        float acc0 = 0.0f, acc1 = 0.0f;
        uint32_t* row = rows + io * PITCH_W;
#pragma unroll
        for (int s = 0; s < 16; s++) {
            float2 pt = *(float2*)(row + 16);
            float da0 = pt.x - ma0, da1 = pt.y - ma1;
            float ta  = fmaf(da0 * da0, qa0, TEN);
            ta        = fmaf(da1 * da1, qa1, ta);
            float ea  = fmaxf(ex2_approx(ta), 1.024e-3f);  // = 1024*max(e,eps)
            float db0 = pt.x - mb0, db1 = pt.y - mb1;
            float tb  = fmaf(db0 * db0, qb0, TEN);
            tb        = fmaf(db1 * db1, qb1, tb);
            float eb  = fmaxf(ex2_approx(tb), 1.024e-3f);
            acc0 += ea;
            acc1 += eb;
            *(__half2*)(row + p) = __floats2half2_rn(ea, eb);
            row += 32 * PITCH_W;
        }
#pragma unroll
        for (int off = 16; off > 0; off >>= 1) {
            acc0 += __shfl_down_sync(0xFFFFFFFFu, acc0, off);
            acc1 += __shfl_down_sync(0xFFFFFFFFu, acc1, off);
        }
        if (io == 0) {
            size_t vb = (size_t)grp * KCOMP + koff;
            vno[ka] = values[vb + ka] / acc0;   // 1024-scales cancel exactly
            vno[kb] = values[vb + kb] / acc1;
        }
    }
    __syncthreads();

    // ---- wait for bias init (set ~30+ us ago; spin is instant) ----
    if (tid == 0) {
        while (*(volatile int*)&g_sync[NGRP] < NWRITERS) { }
        __threadfence();
    }
    __syncthreads();

    // ---- partial weights + gather + scatter (thread = point) ----
    {
        uint32_t* row = rows + tid * PITCH_W;
        float w = 0.0f;
#pragma unroll
        for (int c4 = 0; c4 < 8; c4++) {
            uint2  d = *(uint2*)(row + c4 * 2);     // 4 halfs
            float4 v = *(float4*)(vno + c4 * 4);    // broadcast
            __half2 h01 = *(__half2*)&d.x;
            __half2 h23 = *(__half2*)&d.y;
            w = fmaf(__low2float(h01),  v.x, w);
            w = fmaf(__high2float(h01), v.y, w);
            w = fmaf(__low2float(h23),  v.z, w);
            w = fmaf(__high2float(h23), v.w, w);
        }
        float2 pt = *(float2*)(row + 16);
        int i0 = (int)pt.x;
        int i1 = (int)pt.y;
        float g = x[(size_t)b * CDIM + i1];
        atomicAdd(&y[(size_t)b * CDIM + i0], w * g);
    }
}

// ---------------------------------------------------------------------------
// Launch
// ---------------------------------------------------------------------------
extern "C" void kernel_launch(void* const* d_in, const int* in_sizes, int n_in,
                              void* d_out, int out_size)
{
    const float* x      = (const float*)d_in[0];
    const float* means  = (const float*)d_in[1];
    const float* sigmas = (const float*)d_in[2];
    const float* values = (const float*)d_in[3];
    const float* bias   = (const float*)d_in[4];
    float* y = (float*)d_out;

    // jax_threefry_partitionable split of key(42)
    uint32_t kg0, kg1, kl0, kl1;
    threefry2x32(0u, 42u, 0u, 0u, kg0, kg1);
    threefry2x32(0u, 42u, 0u, 1u, kl0, kl1);

    void* sync_ptr = nullptr;
    cudaGetSymbolAddress(&sync_ptr, g_sync);
    cudaMemsetAsync(sync_ptr, 0, (NGRP + 1) * sizeof(int));

    sparse_fused_kernel<<<NGRP * 2, 512>>>(
        x, means, sigmas, values, bias, y, kg0, kg1, kl0, kl1);
}

// round 14
// speedup vs baseline: 1.3556x; 1.3556x over previous
#include <cuda_runtime.h>
#include <cuda_fp16.h>
#include <cstdint>

// Problem constants
#define BB    8
#define NTOK  16384
#define KCOMP 64
#define CGRP  256       // N / K
#define CDIM  8192      // C_OUT == C_IN
#define IPTS  512       // points per group = K * 8
#define NGRP  (BB * CGRP)       // 2048
#define HK    32        // k's per CTA (K split in 2)
#define NWRITERS 128    // CTAs of points_kernel that also write y = bias

// Row: 32 halfs (dens, scaled e*1024) + float2 point
#define PITCH_W 18      // words per row (16 dens words + 2 point words)

// Global scratch: all integer points, shared by both k-half CTAs
__device__ float2 g_pts[NGRP * IPTS];   // 8 MB

// Bare MUFU.EX2 (no libm wrapper)
__device__ __forceinline__ float ex2_approx(float t)
{
    float r;
    asm("ex2.approx.ftz.f32 %0, %1;" : "=f"(r) : "f"(t));
    return r;
}

// ---- packed f32x2 helpers (Blackwell FFMA2 path, PTX-only) ----
#define PK_F32X2(out, lo, hi) \
    asm("mov.b64 %0, {%1, %2};" : "=l"(out) : "f"(lo), "f"(hi))
#define UNPK_F32X2(lo, hi, in) \
    asm("mov.b64 {%0, %1}, %2;" : "=f"(lo), "=f"(hi) : "l"(in))
#define ADD2(out, a, b) \
    asm("add.rn.f32x2 %0, %1, %2;" : "=l"(out) : "l"(a), "l"(b))
#define MUL2(out, a, b) \
    asm("mul.rn.f32x2 %0, %1, %2;" : "=l"(out) : "l"(a), "l"(b))
#define FMA2(out, a, b, c) \
    asm("fma.rn.f32x2 %0, %1, %2, %3;" : "=l"(out) : "l"(a), "l"(b), "l"(c))

// ---------------------------------------------------------------------------
// threefry2x32 (20 rounds)
// ---------------------------------------------------------------------------
__host__ __device__ __forceinline__
void threefry2x32(uint32_t k0, uint32_t k1, uint32_t x0, uint32_t x1,
                  uint32_t& y0, uint32_t& y1)
{
    uint32_t ks2 = k0 ^ k1 ^ 0x1BD11BDAu;
#define TF_RND(r) { x0 += x1; x1 = (x1 << (r)) | (x1 >> (32 - (r))); x1 ^= x0; }
    x0 += k0; x1 += k1;
    TF_RND(13) TF_RND(15) TF_RND(26) TF_RND(6)
    x0 += k1;  x1 += ks2 + 1u;
    TF_RND(17) TF_RND(29) TF_RND(16) TF_RND(24)
    x0 += ks2; x1 += k0 + 2u;
    TF_RND(13) TF_RND(15) TF_RND(26) TF_RND(6)
    x0 += k0;  x1 += k1 + 3u;
    TF_RND(17) TF_RND(29) TF_RND(16) TF_RND(24)
    x0 += k1;  x1 += ks2 + 4u;
    TF_RND(13) TF_RND(15) TF_RND(26) TF_RND(6)
    x0 += ks2; x1 += k0 + 5u;
#undef TF_RND
    y0 = x0; y1 = x1;
}

// jax partitionable random_bits: counter (0, f); bits = w0 ^ w1
__device__ __forceinline__
float jax_uniform_at(uint32_t k0, uint32_t k1, uint32_t f)
{
    uint32_t y0, y1;
    threefry2x32(k0, k1, 0u, f, y0, y1);
    uint32_t bits = y0 ^ y1;
    return __uint_as_float((bits >> 9) | 0x3F800000u) - 1.0f;
}

// ---------------------------------------------------------------------------
// Kernel 1: generate all points; first 128 CTAs also initialize y = bias.
// ---------------------------------------------------------------------------
__global__ void __launch_bounds__(512)
points_kernel(const float* __restrict__ means,
              const float* __restrict__ bias,
              float* __restrict__ y,
              uint32_t kg0, uint32_t kg1, uint32_t kl0, uint32_t kl1)
{
    __shared__ float us[512];   // uniforms * (1-eps): [0..255]=kg, [256..511]=kl
    const int grp = blockIdx.x;
    const int tid = threadIdx.x;
    const float OME = (float)(1.0 - 1e-6);

    // y = bias (128 CTAs x 512 threads = 65536 = B*C_OUT)
    if (grp < NWRITERS) {
        int o = (grp << 9) | tid;
        y[o] = bias[o & (CDIM - 1)];
    }

    // phase 1: exactly one uniform per thread (balanced warps)
    {
        uint32_t s  = (uint32_t)tid >> 8;
        uint32_t f  = (uint32_t)grp * 256u + ((uint32_t)tid & 255u);
        uint32_t a0 = s ? kl0 : kg0;
        uint32_t a1 = s ? kl1 : kg1;
        us[tid] = jax_uniform_at(a0, a1, f) * OME;
    }
    __syncthreads();

    // phase 2: one point per thread
    const int k = tid >> 3;
    const int j = tid & 7;
    size_t mbase = ((size_t)grp * KCOMP + k) * 2;
    float m0 = means[mbase + 0];
    float m1 = means[mbase + 1];
    float r0, r1;
    if (j < 4) {
        r0 = (j < 2)        ? floorf(m0) : ceilf(m0);
        r1 = ((j & 1) == 0) ? floorf(m1) : ceilf(m1);
    } else {
        int base = (((j >> 1) & 1) << 8) + 4 * k + ((j & 1) << 1);
        float u0 = us[base];
        float u1 = us[base + 1];
        if (j < 6) {
            r0 = floorf(u0 * 8192.0f);
            r1 = floorf(u1 * 8192.0f);
        } else {
            float mr0 = rintf(m0), mr1 = rintf(m1);
            float lo0 = mr0 - 8.0f;
            if (lo0 < 0.0f) lo0 = 0.0f;
            if (mr0 + 8.0f > 8192.0f) lo0 = 8176.0f;
            float lo1 = mr1 - 8.0f;
            if (lo1 < 0.0f) lo1 = 0.0f;
            if (mr1 + 8.0f > 8192.0f) lo1 = 8176.0f;
            r0 = floorf(u0 * 16.0f + lo0);
            r1 = floorf(u1 * 16.0f + lo1);
        }
    }
    r0 = fminf(fmaxf(r0, 0.0f), 8191.0f);
    r1 = fminf(fmaxf(r1, 0.0f), 8191.0f);
    g_pts[grp * IPTS + tid] = make_float2(r0, r1);
}

// ---------------------------------------------------------------------------
// Kernel 2: main. One CTA per (group, k-half). 4 CTAs/SM (36.9 KB smem).
// Density loop uses packed f32x2 (FFMA2) across the (ka, kb) component pair.
// ---------------------------------------------------------------------------
__global__ void __launch_bounds__(512, 4)
sparse_main_kernel(const float* __restrict__ x,
                   const float* __restrict__ means,
                   const float* __restrict__ sigmas,
                   const float* __restrict__ values,
                   float* __restrict__ y)
{
    __shared__ __align__(16) float vno[HK];
    __shared__ float mm0[HK], mm1[HK], qq0[HK], qq1[HK];
    __shared__ uint32_t rows[IPTS * PITCH_W];    // 36864 B

    const int bx   = blockIdx.x;
    const int grp  = bx >> 1;            // consecutive pair shares the group
    const int koff = (bx & 1) * HK;
    const int b    = grp >> 8;
    const int tid  = threadIdx.x;

    const float NHL2E = -0.72134752044448170f;   // -0.5*log2(e)
    const float TEN   = 10.0f;                   // folds the *1024 fp16 scale

    // ---- params for this CTA's 32 components ----
    if (tid < HK) {
        size_t base = ((size_t)grp * KCOMP + koff + tid);
        mm0[tid] = means[base * 2 + 0];
        mm1[tid] = means[base * 2 + 1];
        qq0[tid] = NHL2E / (1e-6f + sigmas[base * 2 + 0]);
        qq1[tid] = NHL2E / (1e-6f + sigmas[base * 2 + 1]);
    }
    // ---- points into row tail ----
    {
        float2 pt = g_pts[grp * IPTS + tid];
        *(float2*)(rows + tid * PITCH_W + 16) = pt;
    }
    __syncthreads();

    // ---- density: warp = 2 components (ka, kb); lane = io over 32 points ----
    {
        const int p  = tid >> 5;         // 0..15 (k-pair)
        const int io = tid & 31;
        const int ka = 2 * p, kb = ka + 1;

        // loop-invariant packed constants: lane0 = component ka, lane1 = kb
        uint64_t nm0, nm1, q0p, q1p, ten2, acc2;
        {
            float a = -mm0[ka], bb2 = -mm0[kb];
            PK_F32X2(nm0, a, bb2);
            float c = -mm1[ka], d = -mm1[kb];
            PK_F32X2(nm1, c, d);
            float e = qq0[ka], f = qq0[kb];
            PK_F32X2(q0p, e, f);
            float g = qq1[ka], h = qq1[kb];
            PK_F32X2(q1p, g, h);
            PK_F32X2(ten2, TEN, TEN);
            float z = 0.0f;
            PK_F32X2(acc2, z, z);
        }

        uint32_t* row = rows + io * PITCH_W;
#pragma unroll
        for (int s = 0; s < 16; s++) {
            float2 pt = *(float2*)(row + 16);
            uint64_t px, py, d0, d1, s0, s1, t;
            PK_F32X2(px, pt.x, pt.x);
            PK_F32X2(py, pt.y, pt.y);
            ADD2(d0, px, nm0);               // (pt.x-ma0, pt.x-mb0)
            ADD2(d1, py, nm1);
            MUL2(s0, d0, d0);
            FMA2(t, s0, q0p, ten2);
            MUL2(s1, d1, d1);
            FMA2(t, s1, q1p, t);
            float tlo, thi;
            UNPK_F32X2(tlo, thi, t);
            float ea = fmaxf(ex2_approx(tlo), 1.024e-3f);  // = 1024*max(e,eps)
            float eb = fmaxf(ex2_approx(thi), 1.024e-3f);
            uint64_t e2;
            PK_F32X2(e2, ea, eb);
            ADD2(acc2, acc2, e2);
            *(__half2*)(row + p) = __floats2half2_rn(ea, eb);
            row += 32 * PITCH_W;
        }
        float acc0, acc1;
        UNPK_F32X2(acc0, acc1, acc2);
#pragma unroll
        for (int off = 16; off > 0; off >>= 1) {
            acc0 += __shfl_down_sync(0xFFFFFFFFu, acc0, off);
            acc1 += __shfl_down_sync(0xFFFFFFFFu, acc1, off);
        }
        if (io == 0) {
            size_t vb = (size_t)grp * KCOMP + koff;
            vno[ka] = values[vb + ka] / acc0;   // 1024-scales cancel exactly
            vno[kb] = values[vb + kb] / acc1;
        }
    }
    __syncthreads();

    // ---- partial weights + gather + scatter (thread = point) ----
    {
        uint32_t* row = rows + tid * PITCH_W;
        float w = 0.0f;
#pragma unroll
        for (int c4 = 0; c4 < 8; c4++) {
            uint2  d = *(uint2*)(row + c4 * 2);     // 4 halfs
            float4 v = *(float4*)(vno + c4 * 4);    // broadcast
            __half2 h01 = *(__half2*)&d.x;
            __half2 h23 = *(__half2*)&d.y;
            w = fmaf(__low2float(h01),  v.x, w);
            w = fmaf(__high2float(h01), v.y, w);
            w = fmaf(__low2float(h23),  v.z, w);
            w = fmaf(__high2float(h23), v.w, w);
        }
        float2 pt = *(float2*)(row + 16);
        int i0 = (int)pt.x;
        int i1 = (int)pt.y;
        float g = x[(size_t)b * CDIM + i1];
        atomicAdd(&y[(size_t)b * CDIM + i0], w * g);
    }
}

// ---------------------------------------------------------------------------
// Launch
// ---------------------------------------------------------------------------
extern "C" void kernel_launch(void* const* d_in, const int* in_sizes, int n_in,
                              void* d_out, int out_size)
{
    const float* x      = (const float*)d_in[0];
    const float* means  = (const float*)d_in[1];
    const float* sigmas = (const float*)d_in[2];
    const float* values = (const float*)d_in[3];
    const float* bias   = (const float*)d_in[4];
    float* y = (float*)d_out;

    // jax_threefry_partitionable split of key(42)
    uint32_t kg0, kg1, kl0, kl1;
    threefry2x32(0u, 42u, 0u, 0u, kg0, kg1);
    threefry2x32(0u, 42u, 0u, 1u, kl0, kl1);

    points_kernel<<<NGRP, 512>>>(means, bias, y, kg0, kg1, kl0, kl1);
    sparse_main_kernel<<<NGRP * 2, 512>>>(x, means, sigmas, values, y);
}